// round 1
// baseline (speedup 1.0000x reference)
#include <cuda_runtime.h>
#include <stdint.h>

#define BATCH   16
#define KTOP    1000
#define MAXP    300
#define NBINS   65536
#define CAP     4096
#define IOU_THRESH 0.65f
#define NTHREADS 1024

// ---------------- scratch (static device globals; no allocation) ------------
__device__ unsigned int       g_hist[BATCH][NBINS];   // 4 MB
__device__ int                g_cnt[BATCH];
__device__ unsigned int       g_T[BATCH];
__device__ unsigned long long g_cand[BATCH][CAP];     // 512 KB

// float -> orderable uint (monotone for all finite floats)
__device__ __forceinline__ unsigned int fkey(float f) {
    unsigned int b = __float_as_uint(f);
    return b ^ ((unsigned int)((int)b >> 31) | 0x80000000u);
}

// ---------------- 1. zero scratch -------------------------------------------
__global__ void k_zero() {
    int i = blockIdx.x * blockDim.x + threadIdx.x;
    if (i < BATCH * NBINS) ((unsigned int*)g_hist)[i] = 0u;
    if (i < BATCH) g_cnt[i] = 0;
}

// ---------------- 2. per-batch histogram of key>>16 -------------------------
__global__ void k_hist(const float* __restrict__ scores, int N) {
    int i4 = blockIdx.x * blockDim.x + threadIdx.x;
    int total4 = BATCH * N / 4;
    if (i4 >= total4) return;
    float4 v = reinterpret_cast<const float4*>(scores)[i4];
    int b = (i4 * 4) / N;              // N % 4 == 0 -> no straddle
    atomicAdd(&g_hist[b][fkey(v.x) >> 16], 1u);
    atomicAdd(&g_hist[b][fkey(v.y) >> 16], 1u);
    atomicAdd(&g_hist[b][fkey(v.z) >> 16], 1u);
    atomicAdd(&g_hist[b][fkey(v.w) >> 16], 1u);
}
__global__ void k_hist_scalar(const float* __restrict__ scores, int N) {
    int i = blockIdx.x * blockDim.x + threadIdx.x;
    if (i >= BATCH * N) return;
    atomicAdd(&g_hist[i / N][fkey(scores[i]) >> 16], 1u);
}

// ---------------- 3. per-batch threshold bin --------------------------------
__global__ void __launch_bounds__(1024) k_thresh() {
    int b = blockIdx.x, tid = threadIdx.x;
    __shared__ unsigned int part[1024];
    const unsigned int* h = g_hist[b];
    unsigned int s = 0;
    #pragma unroll 8
    for (int k = 0; k < 64; ++k) s += h[tid * 64 + k];
    part[tid] = s;
    __syncthreads();
    // inclusive suffix scan over 1024 segment sums
    for (int off = 1; off < 1024; off <<= 1) {
        unsigned int v = part[tid];
        unsigned int add = (tid + off < 1024) ? part[tid + off] : 0u;
        __syncthreads();
        part[tid] = v + add;
        __syncthreads();
    }
    __shared__ int s_seg;
    __shared__ unsigned int s_above;
    if (tid == 0) { s_seg = 0; s_above = 0; }
    __syncthreads();
    unsigned int suf = part[tid];
    unsigned int nxt = (tid < 1023) ? part[tid + 1] : 0u;
    if (suf >= KTOP && nxt < KTOP) { s_seg = tid; s_above = nxt; }
    __syncthreads();
    if (tid == 0) {
        unsigned int cum = s_above;
        int seg = s_seg;
        unsigned int T = (unsigned int)(seg * 64);
        for (int k = 63; k >= 0; --k) {
            cum += h[seg * 64 + k];
            if (cum >= KTOP) { T = (unsigned int)(seg * 64 + k); break; }
        }
        g_T[b] = T;
    }
}

// ---------------- 4. collect candidates (key>>16 >= T) ----------------------
__global__ void k_collect(const float* __restrict__ scores, int N) {
    int i4 = blockIdx.x * blockDim.x + threadIdx.x;
    int total4 = BATCH * N / 4;
    if (i4 >= total4) return;
    int base = i4 * 4;
    int b = base / N;
    unsigned int T = g_T[b];
    float4 v = reinterpret_cast<const float4*>(scores)[i4];
    int li = base - b * N;
    float e0[4] = {v.x, v.y, v.z, v.w};
    #pragma unroll
    for (int e = 0; e < 4; ++e) {
        unsigned int k = fkey(e0[e]);
        if ((k >> 16) >= T) {
            int p = atomicAdd(&g_cnt[b], 1);
            if (p < CAP)
                g_cand[b][p] = ((unsigned long long)k << 32)
                             | (unsigned int)(~(unsigned int)(li + e));
        }
    }
}
__global__ void k_collect_scalar(const float* __restrict__ scores, int N) {
    int i = blockIdx.x * blockDim.x + threadIdx.x;
    if (i >= BATCH * N) return;
    int b = i / N, li = i - b * N;
    unsigned int k = fkey(scores[i]);
    if ((k >> 16) >= g_T[b]) {
        int p = atomicAdd(&g_cnt[b], 1);
        if (p < CAP)
            g_cand[b][p] = ((unsigned long long)k << 32)
                         | (unsigned int)(~(unsigned int)li);
    }
}

// ---------------- 5. per-batch sort + NMS + output --------------------------
__global__ void __launch_bounds__(NTHREADS, 1) k_sortnms(
    const float* __restrict__ boxes, const int* __restrict__ classes,
    float* __restrict__ out, int N)
{
    __shared__ unsigned long long s_sort[CAP];   // 32 KB; aliased by s_bb/s_box later
    __shared__ int            s_idx[KTOP];
    __shared__ float          s_score[KTOP];
    __shared__ int            s_cls[KTOP];
    __shared__ unsigned char  s_keep[KTOP];
    __shared__ int            s_out[MAXP];
    __shared__ float          s_red[32];
    __shared__ float          s_maxc;

    int b = blockIdx.x, tid = threadIdx.x;
    int n = min(g_cnt[b], CAP);
    for (int i = tid; i < CAP; i += NTHREADS)
        s_sort[i] = (i < n) ? g_cand[b][i] : 0ULL;
    __syncthreads();

    // bitonic sort ascending; top-K read from the high end (== descending)
    for (int k = 2; k <= CAP; k <<= 1) {
        for (int j = k >> 1; j > 0; j >>= 1) {
            #pragma unroll
            for (int t0 = 0; t0 < CAP; t0 += NTHREADS) {
                int t = t0 + tid;
                int ixj = t ^ j;
                if (ixj > t) {
                    bool up = ((t & k) == 0);
                    unsigned long long a = s_sort[t], c = s_sort[ixj];
                    if ((a > c) == up) { s_sort[t] = c; s_sort[ixj] = a; }
                }
            }
            __syncthreads();
        }
    }

    // gather rank r = s_sort[CAP-1-r]; score recovered from key bits
    if (tid < KTOP) {
        unsigned long long comp = s_sort[CAP - 1 - tid];
        unsigned int key = (unsigned int)(comp >> 32);
        unsigned int bits = (key & 0x80000000u) ? (key ^ 0x80000000u) : ~key;
        s_score[tid] = __uint_as_float(bits);
        int idx = (int)(~(unsigned int)comp);
        s_idx[tid] = min(max(idx, 0), N - 1);
    }
    __syncthreads();   // after this, s_sort region is reusable

    float* s_bb  = reinterpret_cast<float*>(s_sort);         // [KTOP*4]
    float* s_box = reinterpret_cast<float*>(s_sort) + 4096;  // [KTOP*4]

    float4 mybox = make_float4(0.f, 0.f, 0.f, 0.f);
    int mycls = 0;
    float mymax = -3.0e38f;
    if (tid < KTOP) {
        long long g = (long long)b * N + s_idx[tid];
        mybox = reinterpret_cast<const float4*>(boxes)[g];
        mycls = classes[g];
        mymax = fmaxf(fmaxf(mybox.x, mybox.y), fmaxf(mybox.z, mybox.w));
    }
    // block max over all gathered coords
    #pragma unroll
    for (int o = 16; o > 0; o >>= 1)
        mymax = fmaxf(mymax, __shfl_xor_sync(0xffffffffu, mymax, o));
    if ((tid & 31) == 0) s_red[tid >> 5] = mymax;
    __syncthreads();
    if (tid < 32) {
        float v = s_red[tid];
        #pragma unroll
        for (int o = 16; o > 0; o >>= 1)
            v = fmaxf(v, __shfl_xor_sync(0xffffffffu, v, o));
        if (tid == 0) s_maxc = __fadd_rn(v, 1.0f);
    }
    __syncthreads();

    float ax1 = 0.f, ay1 = 0.f, ax2 = 0.f, ay2 = 0.f, aarea = 0.f;
    int keepReg = 0;
    if (tid < KTOP) {
        float off = __fmul_rn((float)mycls, s_maxc);
        ax1 = __fadd_rn(mybox.x, off);
        ay1 = __fadd_rn(mybox.y, off);
        ax2 = __fadd_rn(mybox.z, off);
        ay2 = __fadd_rn(mybox.w, off);
        aarea = __fmul_rn(__fsub_rn(ax2, ax1), __fsub_rn(ay2, ay1));
        s_bb[tid*4+0] = ax1; s_bb[tid*4+1] = ay1;
        s_bb[tid*4+2] = ax2; s_bb[tid*4+3] = ay2;
        s_box[tid*4+0] = mybox.x; s_box[tid*4+1] = mybox.y;
        s_box[tid*4+2] = mybox.z; s_box[tid*4+3] = mybox.w;
        s_cls[tid] = mycls;
        s_keep[tid] = 1;
        keepReg = 1;
    }

    // greedy NMS; stop once 300 kept (later suppressions can't affect output)
    int cnt = 0;
    for (int i = 0; i < KTOP; ++i) {
        __syncthreads();
        if (s_keep[i]) {
            if (tid == 0) s_out[cnt] = i;
            ++cnt;
            if (cnt == MAXP) break;
            if (keepReg && tid > i) {
                float bx1 = s_bb[i*4+0], by1 = s_bb[i*4+1];
                float bx2 = s_bb[i*4+2], by2 = s_bb[i*4+3];
                float barea = __fmul_rn(__fsub_rn(bx2, bx1), __fsub_rn(by2, by1));
                float ix1 = fmaxf(ax1, bx1), iy1 = fmaxf(ay1, by1);
                float ix2 = fminf(ax2, bx2), iy2 = fminf(ay2, by2);
                float w = fmaxf(__fsub_rn(ix2, ix1), 0.0f);
                float h = fmaxf(__fsub_rn(iy2, iy1), 0.0f);
                float inter = __fmul_rn(w, h);
                float den = __fadd_rn(__fsub_rn(__fadd_rn(barea, aarea), inter), 1e-9f);
                if (__fdiv_rn(inter, den) > IOU_THRESH) {
                    keepReg = 0;
                    s_keep[tid] = 0;
                }
            }
        }
    }
    __syncthreads();

    for (int e = tid; e < MAXP * 6; e += NTHREADS) {
        int p = e / 6, c = e - p * 6;
        float v = 0.0f;
        if (p < cnt) {
            int r = s_out[p];
            v = (c < 4) ? s_box[r*4+c] : (c == 4) ? s_score[r] : (float)s_cls[r];
        }
        out[b * (MAXP * 6) + e] = v;
    }
}

// ---------------- launch ----------------------------------------------------
extern "C" void kernel_launch(void* const* d_in, const int* in_sizes, int n_in,
                              void* d_out, int out_size) {
    const float* boxes   = (const float*)d_in[0];
    const float* scores  = (const float*)d_in[1];
    const int*   classes = (const int*)d_in[2];
    float* out = (float*)d_out;
    int N = in_sizes[1] / BATCH;
    int total = BATCH * N;

    k_zero<<<(BATCH * NBINS + 255) / 256, 256>>>();
    if ((N & 3) == 0) {
        int total4 = total / 4;
        k_hist<<<(total4 + 255) / 256, 256>>>(scores, N);
        k_thresh<<<BATCH, 1024>>>();
        k_collect<<<(total4 + 255) / 256, 256>>>(scores, N);
    } else {
        k_hist_scalar<<<(total + 255) / 256, 256>>>(scores, N);
        k_thresh<<<BATCH, 1024>>>();
        k_collect_scalar<<<(total + 255) / 256, 256>>>(scores, N);
    }
    k_sortnms<<<BATCH, NTHREADS>>>(boxes, classes, out, N);
}

// round 3
// speedup vs baseline: 1.2582x; 1.2582x over previous
#include <cuda_runtime.h>
#include <stdint.h>

#define BATCH   16
#define KTOP    1000
#define MAXP    300
#define NBINS   65536
#define CAP     4096
#define IOU_THRESH 0.65f
#define T1      0.9965f
#define NT      1024
#define CHUNK   128

// ---------------- scratch (static device globals) ---------------------------
__device__ unsigned int       g_hist[BATCH][NBINS];   // only touched on fallback
__device__ int                g_cnt[BATCH];
__device__ int                g_need[BATCH];
__device__ unsigned int       g_T[BATCH];
__device__ unsigned long long g_cand[BATCH][CAP];

// float -> orderable uint (monotone for all finite floats)
__device__ __forceinline__ unsigned int fkey(float f) {
    unsigned int b = __float_as_uint(f);
    return b ^ ((unsigned int)((int)b >> 31) | 0x80000000u);
}

__device__ __forceinline__ void push_cand(int b, float s, int idx) {
    int p = atomicAdd(&g_cnt[b], 1);
    if (p < CAP)
        g_cand[b][p] = ((unsigned long long)fkey(s) << 32)
                     | (unsigned int)(~(unsigned int)idx);
}

// ---------------- 0. init ---------------------------------------------------
__global__ void k_init() {
    if (threadIdx.x < BATCH) { g_cnt[threadIdx.x] = 0; g_need[threadIdx.x] = 0; }
}

// ---------------- 1. fast collect with static threshold ---------------------
__global__ void k_collect1(const float* __restrict__ scores, int N) {
    int b = blockIdx.y;
    size_t base = (size_t)b * N;
    int stride = gridDim.x * blockDim.x;
    int t0 = blockIdx.x * blockDim.x + threadIdx.x;
    if ((N & 3) == 0) {
        const float4* p = reinterpret_cast<const float4*>(scores + base);
        int N4 = N >> 2;
        for (int t = t0; t < N4; t += stride) {
            float4 v = p[t];
            int i0 = t << 2;
            if (v.x >= T1) push_cand(b, v.x, i0 + 0);
            if (v.y >= T1) push_cand(b, v.y, i0 + 1);
            if (v.z >= T1) push_cand(b, v.z, i0 + 2);
            if (v.w >= T1) push_cand(b, v.w, i0 + 3);
        }
    } else {
        for (int i = t0; i < N; i += stride) {
            float s = scores[base + i];
            if (s >= T1) push_cand(b, s, i);
        }
    }
}

// ---------------- 2. check: do we need the exact fallback? ------------------
__global__ void k_check() {
    int b = threadIdx.x;
    if (b >= BATCH) return;
    int n = g_cnt[b];
    int need = (n < KTOP || n > CAP) ? 1 : 0;
    g_need[b] = need;
    if (need) g_cnt[b] = 0;
}

// ---------------- fallback: zero hist (flagged batches only) ----------------
__global__ void k_zeroF() {
    int b = blockIdx.y;
    if (!g_need[b]) return;
    int base = blockIdx.x * 1024;          // 64 blocks x 1024 bins
    for (int k = threadIdx.x; k < 1024; k += blockDim.x)
        g_hist[b][base + k] = 0u;
}

// ---------------- fallback: histogram of key>>16 ----------------------------
__global__ void k_histF(const float* __restrict__ scores, int N) {
    int b = blockIdx.y;
    if (!g_need[b]) return;
    size_t base = (size_t)b * N;
    int stride = gridDim.x * blockDim.x;
    for (int i = blockIdx.x * blockDim.x + threadIdx.x; i < N; i += stride)
        atomicAdd(&g_hist[b][fkey(scores[base + i]) >> 16], 1u);
}

// ---------------- fallback: per-batch threshold bin -------------------------
__global__ void __launch_bounds__(1024) k_threshF() {
    int b = blockIdx.x, tid = threadIdx.x;
    if (!g_need[b]) return;
    __shared__ unsigned int part[1024];
    const unsigned int* h = g_hist[b];
    unsigned int s = 0;
    #pragma unroll 8
    for (int k = 0; k < 64; ++k) s += h[tid * 64 + k];
    part[tid] = s;
    __syncthreads();
    for (int off = 1; off < 1024; off <<= 1) {
        unsigned int v = part[tid];
        unsigned int add = (tid + off < 1024) ? part[tid + off] : 0u;
        __syncthreads();
        part[tid] = v + add;
        __syncthreads();
    }
    __shared__ int s_seg;
    __shared__ unsigned int s_above;
    if (tid == 0) { s_seg = 0; s_above = 0; }
    __syncthreads();
    unsigned int suf = part[tid];
    unsigned int nxt = (tid < 1023) ? part[tid + 1] : 0u;
    if (suf >= KTOP && nxt < KTOP) { s_seg = tid; s_above = nxt; }
    __syncthreads();
    if (tid == 0) {
        unsigned int cum = s_above;
        int seg = s_seg;
        unsigned int T = (unsigned int)(seg * 64);
        for (int k = 63; k >= 0; --k) {
            cum += h[seg * 64 + k];
            if (cum >= KTOP) { T = (unsigned int)(seg * 64 + k); break; }
        }
        g_T[b] = T;
    }
}

// ---------------- fallback: exact collect -----------------------------------
__global__ void k_collect2F(const float* __restrict__ scores, int N) {
    int b = blockIdx.y;
    if (!g_need[b]) return;
    unsigned int T = g_T[b];
    size_t base = (size_t)b * N;
    int stride = gridDim.x * blockDim.x;
    for (int i = blockIdx.x * blockDim.x + threadIdx.x; i < N; i += stride) {
        float s = scores[base + i];
        if ((fkey(s) >> 16) >= T) push_cand(b, s, i);
    }
}

// ---------------- dynamic smem layout for k_sortnms -------------------------
#define SUP_BYTES   (KTOP * 32 * 4)            /* 128000; aliases u64 key[4096] */
#define P1_OFF      SUP_BYTES                  /* float2[1024]  8192 */
#define P2_OFF      (P1_OFF + 8192)            /* float2[1024]  8192 */
#define AREA_OFF    (P2_OFF + 8192)            /* float[1024]   4096 */
#define SCORE_OFF   (AREA_OFF + 4096)          /* float[1024]   4096 */
#define OBOX_OFF    (SCORE_OFF + 4096)         /* float4[1024] 16384 */
#define CLS_OFF     (OBOX_OFF + 16384)         /* int[1024]     4096 */
#define OUTI_OFF    (CLS_OFF + 4096)           /* int[320]      1280 */
#define RED_OFF     (OUTI_OFF + 1280)          /* float[32]      128 */
#define MISC_OFF    (RED_OFF + 128)            /* ints + maxc     32 */
#define SMEM_BYTES  (MISC_OFF + 32)            /* = 174496 */

// ---------------- 3. per-batch sort + NMS + output --------------------------
__global__ void __launch_bounds__(NT, 1) k_sortnms(
    const float* __restrict__ boxes, const int* __restrict__ classes,
    float* __restrict__ out, int N)
{
    extern __shared__ unsigned char sm[];
    unsigned long long* s_key = (unsigned long long*)sm;        // phase A
    unsigned int*       s_sup = (unsigned int*)sm;              // phase C (alias)
    float2* s_p1    = (float2*)(sm + P1_OFF);
    float2* s_p2    = (float2*)(sm + P2_OFF);
    float*  s_area  = (float*) (sm + AREA_OFF);
    float*  s_score = (float*) (sm + SCORE_OFF);
    float4* s_obox  = (float4*)(sm + OBOX_OFF);
    int*    s_cls   = (int*)   (sm + CLS_OFF);
    int*    s_out   = (int*)   (sm + OUTI_OFF);
    float*  s_red   = (float*) (sm + RED_OFF);
    int*    s_misc  = (int*)   (sm + MISC_OFF);   // [0]=done [1]=cnt [2]=maxc(float)

    int b = blockIdx.x, tid = threadIdx.x;
    int n = min(g_cnt[b], CAP);
    int M = (n <= 2048) ? 2048 : 4096;

    if (tid == 0) { s_misc[0] = 0; s_misc[1] = 0; }
    for (int i = tid; i < M; i += NT)
        s_key[i] = (i < n) ? g_cand[b][i] : 0ULL;
    __syncthreads();

    // ---- bitonic sort ascending over M elements ----
    for (int k = 2; k <= M; k <<= 1) {
        for (int j = k >> 1; j > 0; j >>= 1) {
            for (int t = tid; t < M; t += NT) {
                int ixj = t ^ j;
                if (ixj > t) {
                    unsigned long long a = s_key[t], c = s_key[ixj];
                    bool up = ((t & k) == 0);
                    if ((a > c) == up) { s_key[t] = c; s_key[ixj] = a; }
                }
            }
            __syncthreads();
        }
    }

    // ---- extract top-K, gather boxes ----
    float maxl = -3.4e38f;
    float4 mybox = make_float4(0.f, 0.f, 0.f, 0.f);
    int mycls = 0;
    if (tid < KTOP) {
        unsigned long long comp = s_key[M - 1 - tid];
        unsigned int key = (unsigned int)(comp >> 32);
        unsigned int bits = (key & 0x80000000u) ? (key ^ 0x80000000u) : ~key;
        s_score[tid] = __uint_as_float(bits);
        int idx = (int)(~(unsigned int)comp);
        idx = min(max(idx, 0), N - 1);
        size_t g = (size_t)b * N + idx;
        mybox = reinterpret_cast<const float4*>(boxes)[g];
        mycls = classes[g];
        s_obox[tid] = mybox;
        s_cls[tid]  = mycls;
        maxl = fmaxf(fmaxf(mybox.x, mybox.y), fmaxf(mybox.z, mybox.w));
    }
    // block max of all gathered coords
    #pragma unroll
    for (int o = 16; o > 0; o >>= 1)
        maxl = fmaxf(maxl, __shfl_xor_sync(0xffffffffu, maxl, o));
    if ((tid & 31) == 0) s_red[tid >> 5] = maxl;
    __syncthreads();
    if (tid < 32) {
        float v = s_red[tid];
        #pragma unroll
        for (int o = 16; o > 0; o >>= 1)
            v = fmaxf(v, __shfl_xor_sync(0xffffffffu, v, o));
        if (tid == 0) ((float*)s_misc)[2] = __fadd_rn(v, 1.0f);
    }
    __syncthreads();
    float maxc = ((float*)s_misc)[2];

    if (tid < KTOP) {
        float off = __fmul_rn((float)mycls, maxc);
        float ax1 = __fadd_rn(mybox.x, off);
        float ay1 = __fadd_rn(mybox.y, off);
        float ax2 = __fadd_rn(mybox.z, off);
        float ay2 = __fadd_rn(mybox.w, off);
        s_p1[tid] = make_float2(ax1, ay1);
        s_p2[tid] = make_float2(ax2, ay2);
        s_area[tid] = __fmul_rn(__fsub_rn(ax2, ax1), __fsub_rn(ay2, ay1));
    }
    __syncthreads();   // s_key no longer needed; sup region free

    // ---- chunked suppression matrix + single-warp bitmask scan ----
    unsigned int keep = 0u;
    if (tid < 32) keep = (tid < 31) ? 0xffffffffu : 0x000000FFu;  // bits j<1000
    int cnt = 0, done = 0;

    for (int c0 = 0; c0 < KTOP; c0 += CHUNK) {
        int c1 = min(c0 + CHUNK, KTOP);
        // fill rows [c0,c1): word W = i*32 + w
        for (int W = c0 * 32 + tid; W < c1 * 32; W += NT) {
            int i = W >> 5, w = W & 31;
            float2 a1 = s_p1[i], a2 = s_p2[i];
            float aarea = s_area[i];
            unsigned int bits = 0u;
            int jlo = w * 32;  if (jlo <= i) jlo = i + 1;
            int jhi = w * 32 + 32;  if (jhi > KTOP) jhi = KTOP;
            for (int j = jlo; j < jhi; ++j) {
                float2 b1 = s_p1[j], b2 = s_p2[j];
                float ix1 = fmaxf(a1.x, b1.x);
                float iy1 = fmaxf(a1.y, b1.y);
                float ix2 = fminf(a2.x, b2.x);
                float iy2 = fminf(a2.y, b2.y);
                float ww = fmaxf(__fsub_rn(ix2, ix1), 0.0f);
                float hh = fmaxf(__fsub_rn(iy2, iy1), 0.0f);
                float inter = __fmul_rn(ww, hh);
                if (inter > 0.0f) {
                    float den = __fadd_rn(
                        __fsub_rn(__fadd_rn(aarea, s_area[j]), inter), 1e-9f);
                    if (__fdiv_rn(inter, den) > IOU_THRESH)
                        bits |= 1u << (j & 31);
                }
            }
            s_sup[i * 32 + w] = bits;
        }
        __syncthreads();
        if (tid < 32) {   // warp 0: serial scan of this chunk
            for (int i = c0; i < c1; ++i) {
                unsigned int kw = __shfl_sync(0xffffffffu, keep, i >> 5);
                if ((kw >> (i & 31)) & 1u) {
                    if (tid == 0) s_out[cnt] = i;
                    ++cnt;
                    if (cnt == MAXP) { done = 1; break; }
                    keep &= ~s_sup[i * 32 + tid];
                }
            }
            if (tid == 0) { s_misc[1] = cnt; s_misc[0] = done; }
        }
        __syncthreads();
        if (s_misc[0]) break;
    }

    int outc = s_misc[1];
    for (int e = tid; e < MAXP * 6; e += NT) {
        int p = e / 6, c = e - p * 6;
        float v = 0.0f;
        if (p < outc) {
            int r = s_out[p];
            float4 bx = s_obox[r];
            v = (c == 0) ? bx.x : (c == 1) ? bx.y : (c == 2) ? bx.z :
                (c == 3) ? bx.w : (c == 4) ? s_score[r] : (float)s_cls[r];
        }
        out[b * (MAXP * 6) + e] = v;
    }
}

// ---------------- launch ----------------------------------------------------
extern "C" void kernel_launch(void* const* d_in, const int* in_sizes, int n_in,
                              void* d_out, int out_size) {
    const float* boxes   = (const float*)d_in[0];
    const float* scores  = (const float*)d_in[1];
    const int*   classes = (const int*)d_in[2];
    float* out = (float*)d_out;
    int N = in_sizes[1] / BATCH;

    cudaFuncSetAttribute(k_sortnms,
        cudaFuncAttributeMaxDynamicSharedMemorySize, SMEM_BYTES);

    k_init<<<1, 32>>>();
    dim3 gc(128, BATCH);
    k_collect1<<<gc, 256>>>(scores, N);
    k_check<<<1, 32>>>();
    dim3 gz(64, BATCH);
    k_zeroF<<<gz, 256>>>();
    k_histF<<<gc, 256>>>(scores, N);
    k_threshF<<<BATCH, 1024>>>();
    k_collect2F<<<gc, 256>>>(scores, N);
    k_sortnms<<<BATCH, NT, SMEM_BYTES>>>(boxes, classes, out, N);
}

// round 4
// speedup vs baseline: 3.7361x; 2.9695x over previous
#include <cuda_runtime.h>
#include <stdint.h>

#define BATCH   16
#define KTOP    1000
#define MAXP    300
#define NBINS   65536
#define CAP     4096
#define IOU_THRESH 0.65f
#define T1      0.9965f
#define NT      1024
#define CHUNK   128

// ---------------- scratch (static device globals) ---------------------------
__device__ unsigned int       g_hist[BATCH][NBINS];   // only touched on fallback
__device__ int                g_cnt[BATCH];
__device__ int                g_need[BATCH];
__device__ unsigned int       g_T[BATCH];
__device__ unsigned long long g_cand[BATCH][CAP];

// float -> orderable uint (monotone for all finite floats)
__device__ __forceinline__ unsigned int fkey(float f) {
    unsigned int b = __float_as_uint(f);
    return b ^ ((unsigned int)((int)b >> 31) | 0x80000000u);
}

__device__ __forceinline__ void push_cand(int b, float s, int idx) {
    int p = atomicAdd(&g_cnt[b], 1);
    if (p < CAP)
        g_cand[b][p] = ((unsigned long long)fkey(s) << 32)
                     | (unsigned int)(~(unsigned int)idx);
}

// ---------------- 0. init ---------------------------------------------------
__global__ void k_init() {
    if (threadIdx.x < BATCH) { g_cnt[threadIdx.x] = 0; g_need[threadIdx.x] = 0; }
}

// ---------------- 1. fast collect with static threshold (MLP-4) -------------
__global__ void __launch_bounds__(512) k_collect1(const float* __restrict__ scores, int N) {
    int b = blockIdx.y;
    size_t base = (size_t)b * N;
    int stride = gridDim.x * blockDim.x;
    int t0 = blockIdx.x * blockDim.x + threadIdx.x;
    if ((N & 3) == 0) {
        const float4* p = reinterpret_cast<const float4*>(scores + base);
        int N4 = N >> 2;
        int t = t0;
        for (; t + 3 * stride < N4; t += 4 * stride) {
            float4 v0 = p[t];
            float4 v1 = p[t + stride];
            float4 v2 = p[t + 2 * stride];
            float4 v3 = p[t + 3 * stride];
            #pragma unroll
            for (int k = 0; k < 4; ++k) {
                float4 v = (k == 0) ? v0 : (k == 1) ? v1 : (k == 2) ? v2 : v3;
                int i0 = (t + k * stride) << 2;
                float m = fmaxf(fmaxf(v.x, v.y), fmaxf(v.z, v.w));
                if (m >= T1) {
                    if (v.x >= T1) push_cand(b, v.x, i0 + 0);
                    if (v.y >= T1) push_cand(b, v.y, i0 + 1);
                    if (v.z >= T1) push_cand(b, v.z, i0 + 2);
                    if (v.w >= T1) push_cand(b, v.w, i0 + 3);
                }
            }
        }
        for (; t < N4; t += stride) {
            float4 v = p[t];
            int i0 = t << 2;
            float m = fmaxf(fmaxf(v.x, v.y), fmaxf(v.z, v.w));
            if (m >= T1) {
                if (v.x >= T1) push_cand(b, v.x, i0 + 0);
                if (v.y >= T1) push_cand(b, v.y, i0 + 1);
                if (v.z >= T1) push_cand(b, v.z, i0 + 2);
                if (v.w >= T1) push_cand(b, v.w, i0 + 3);
            }
        }
    } else {
        for (int i = t0; i < N; i += stride) {
            float s = scores[base + i];
            if (s >= T1) push_cand(b, s, i);
        }
    }
}

// ---------------- 2. check: do we need the exact fallback? ------------------
__global__ void k_check() {
    int b = threadIdx.x;
    if (b >= BATCH) return;
    int n = g_cnt[b];
    int need = (n < KTOP || n > CAP) ? 1 : 0;
    g_need[b] = need;
    if (need) g_cnt[b] = 0;
}

// ---------------- fallback: zero hist (flagged batches only) ----------------
__global__ void k_zeroF() {
    int b = blockIdx.y;
    if (!g_need[b]) return;
    int base = blockIdx.x * (NBINS / 8);       // 8 blocks per batch
    for (int k = threadIdx.x; k < NBINS / 8; k += blockDim.x)
        g_hist[b][base + k] = 0u;
}

// ---------------- fallback: histogram of key>>16 ----------------------------
__global__ void k_histF(const float* __restrict__ scores, int N) {
    int b = blockIdx.y;
    if (!g_need[b]) return;
    size_t base = (size_t)b * N;
    int stride = gridDim.x * blockDim.x;
    for (int i = blockIdx.x * blockDim.x + threadIdx.x; i < N; i += stride)
        atomicAdd(&g_hist[b][fkey(scores[base + i]) >> 16], 1u);
}

// ---------------- fallback: per-batch threshold bin -------------------------
__global__ void __launch_bounds__(1024) k_threshF() {
    int b = blockIdx.x, tid = threadIdx.x;
    if (!g_need[b]) return;
    __shared__ unsigned int part[1024];
    const unsigned int* h = g_hist[b];
    unsigned int s = 0;
    #pragma unroll 8
    for (int k = 0; k < 64; ++k) s += h[tid * 64 + k];
    part[tid] = s;
    __syncthreads();
    for (int off = 1; off < 1024; off <<= 1) {
        unsigned int v = part[tid];
        unsigned int add = (tid + off < 1024) ? part[tid + off] : 0u;
        __syncthreads();
        part[tid] = v + add;
        __syncthreads();
    }
    __shared__ int s_seg;
    __shared__ unsigned int s_above;
    if (tid == 0) { s_seg = 0; s_above = 0; }
    __syncthreads();
    unsigned int suf = part[tid];
    unsigned int nxt = (tid < 1023) ? part[tid + 1] : 0u;
    if (suf >= KTOP && nxt < KTOP) { s_seg = tid; s_above = nxt; }
    __syncthreads();
    if (tid == 0) {
        unsigned int cum = s_above;
        int seg = s_seg;
        unsigned int T = (unsigned int)(seg * 64);
        for (int k = 63; k >= 0; --k) {
            cum += h[seg * 64 + k];
            if (cum >= KTOP) { T = (unsigned int)(seg * 64 + k); break; }
        }
        g_T[b] = T;
    }
}

// ---------------- fallback: exact collect -----------------------------------
__global__ void k_collect2F(const float* __restrict__ scores, int N) {
    int b = blockIdx.y;
    if (!g_need[b]) return;
    unsigned int T = g_T[b];
    size_t base = (size_t)b * N;
    int stride = gridDim.x * blockDim.x;
    for (int i = blockIdx.x * blockDim.x + threadIdx.x; i < N; i += stride) {
        float s = scores[base + i];
        if ((fkey(s) >> 16) >= T) push_cand(b, s, i);
    }
}

// ---------------- dynamic smem layout for k_sortnms -------------------------
#define SUP_BYTES   (KTOP * 32 * 4)            /* 128000; aliases u64 key[4096] */
#define P1_OFF      SUP_BYTES                  /* float2[1024]  8192 */
#define P2_OFF      (P1_OFF + 8192)            /* float2[1024]  8192 */
#define AREA_OFF    (P2_OFF + 8192)            /* float[1024]   4096 */
#define SCORE_OFF   (AREA_OFF + 4096)          /* float[1024]   4096 */
#define OBOX_OFF    (SCORE_OFF + 4096)         /* float4[1024] 16384 */
#define CLS_OFF     (OBOX_OFF + 16384)         /* int[1024]     4096 */
#define OUTI_OFF    (CLS_OFF + 4096)           /* int[320]      1280 */
#define RED_OFF     (OUTI_OFF + 1280)          /* float[32]      128 */
#define MISC_OFF    (RED_OFF + 128)            /* ints + maxc     32 */
#define SMEM_BYTES  (MISC_OFF + 32)            /* = 174496 */

// ---------------- 3. per-batch sort + NMS + output --------------------------
__global__ void __launch_bounds__(NT, 1) k_sortnms(
    const float* __restrict__ boxes, const int* __restrict__ classes,
    float* __restrict__ out, int N)
{
    extern __shared__ unsigned char sm[];
    unsigned long long* s_key = (unsigned long long*)sm;        // phase A
    unsigned int*       s_sup = (unsigned int*)sm;              // phase C (alias)
    float2* s_p1    = (float2*)(sm + P1_OFF);
    float2* s_p2    = (float2*)(sm + P2_OFF);
    float*  s_area  = (float*) (sm + AREA_OFF);
    float*  s_score = (float*) (sm + SCORE_OFF);
    float4* s_obox  = (float4*)(sm + OBOX_OFF);
    int*    s_cls   = (int*)   (sm + CLS_OFF);
    int*    s_out   = (int*)   (sm + OUTI_OFF);
    float*  s_red   = (float*) (sm + RED_OFF);
    int*    s_misc  = (int*)   (sm + MISC_OFF);   // [0]=done [1]=cnt [2]=maxc(float)

    int b = blockIdx.x, tid = threadIdx.x;
    int lane = tid & 31, wid = tid >> 5;
    int n = min(g_cnt[b], CAP);
    int M = (n <= 2048) ? 2048 : 4096;

    if (tid == 0) { s_misc[0] = 0; s_misc[1] = 0; }
    for (int i = tid; i < M; i += NT)
        s_key[i] = (i < n) ? g_cand[b][i] : 0ULL;
    __syncthreads();

    // ---- bitonic sort ascending over M elements ----
    for (int k = 2; k <= M; k <<= 1) {
        for (int j = k >> 1; j > 0; j >>= 1) {
            for (int t = tid; t < M; t += NT) {
                int ixj = t ^ j;
                if (ixj > t) {
                    unsigned long long a = s_key[t], c = s_key[ixj];
                    bool up = ((t & k) == 0);
                    if ((a > c) == up) { s_key[t] = c; s_key[ixj] = a; }
                }
            }
            __syncthreads();
        }
    }

    // ---- extract top-K, gather boxes ----
    float maxl = -3.4e38f;
    float4 mybox = make_float4(0.f, 0.f, 0.f, 0.f);
    int mycls = 0;
    if (tid < KTOP) {
        unsigned long long comp = s_key[M - 1 - tid];
        unsigned int key = (unsigned int)(comp >> 32);
        unsigned int bits = (key & 0x80000000u) ? (key ^ 0x80000000u) : ~key;
        s_score[tid] = __uint_as_float(bits);
        int idx = (int)(~(unsigned int)comp);
        idx = min(max(idx, 0), N - 1);
        size_t g = (size_t)b * N + idx;
        mybox = reinterpret_cast<const float4*>(boxes)[g];
        mycls = classes[g];
        s_obox[tid] = mybox;
        s_cls[tid]  = mycls;
        maxl = fmaxf(fmaxf(mybox.x, mybox.y), fmaxf(mybox.z, mybox.w));
    }
    // block max of all gathered coords
    #pragma unroll
    for (int o = 16; o > 0; o >>= 1)
        maxl = fmaxf(maxl, __shfl_xor_sync(0xffffffffu, maxl, o));
    if (lane == 0) s_red[wid] = maxl;
    __syncthreads();
    if (tid < 32) {
        float v = s_red[tid];
        #pragma unroll
        for (int o = 16; o > 0; o >>= 1)
            v = fmaxf(v, __shfl_xor_sync(0xffffffffu, v, o));
        if (tid == 0) ((float*)s_misc)[2] = __fadd_rn(v, 1.0f);
    }
    __syncthreads();
    float maxc = ((float*)s_misc)[2];

    if (tid < KTOP) {
        float off = __fmul_rn((float)mycls, maxc);
        float ax1 = __fadd_rn(mybox.x, off);
        float ay1 = __fadd_rn(mybox.y, off);
        float ax2 = __fadd_rn(mybox.z, off);
        float ay2 = __fadd_rn(mybox.w, off);
        s_p1[tid] = make_float2(ax1, ay1);
        s_p2[tid] = make_float2(ax2, ay2);
        s_area[tid] = __fmul_rn(__fsub_rn(ax2, ax1), __fsub_rn(ay2, ay1));
    }
    __syncthreads();   // s_key no longer needed; sup region free

    // ---- chunked suppression matrix (warp-per-row, ballot) + 1-warp scan ----
    unsigned int keep = 0u;
    if (tid < 32) keep = (tid < 31) ? 0xffffffffu : 0x000000FFu;  // bits j<1000
    int cnt = 0;

    for (int c0 = 0; c0 < KTOP; c0 += CHUNK) {
        int c1 = min(c0 + CHUNK, KTOP);
        // one warp per row r; lanes sweep consecutive j (conflict-free LDS)
        for (int r = c0 + wid; r < c1; r += 32) {
            float2 a1 = s_p1[r], a2 = s_p2[r];          // uniform broadcast
            float aarea = s_area[r];
            int jb0 = r >> 5;
            // zero words strictly below the diagonal word
            for (int jb = lane; jb < jb0; jb += 32)
                s_sup[r * 32 + jb] = 0u;
            for (int jb = jb0; jb < 32; ++jb) {
                int j = jb * 32 + lane;
                bool ok = (j > r) & (j < KTOP);
                float inter = 0.0f, jarea = 0.0f;
                if (ok) {
                    float2 b1 = s_p1[j], b2 = s_p2[j];  // coalesced
                    float ix1 = fmaxf(a1.x, b1.x);
                    float iy1 = fmaxf(a1.y, b1.y);
                    float ix2 = fminf(a2.x, b2.x);
                    float iy2 = fminf(a2.y, b2.y);
                    float ww = fmaxf(__fsub_rn(ix2, ix1), 0.0f);
                    float hh = fmaxf(__fsub_rn(iy2, iy1), 0.0f);
                    inter = __fmul_rn(ww, hh);
                    jarea = s_area[j];
                }
                unsigned int anyo = __ballot_sync(0xffffffffu, ok && inter > 0.0f);
                unsigned int bits = 0u;
                if (anyo) {   // rare: compute exact IoU only where overlap exists
                    bool sup = false;
                    if (ok && inter > 0.0f) {
                        float den = __fadd_rn(
                            __fsub_rn(__fadd_rn(aarea, jarea), inter), 1e-9f);
                        sup = __fdiv_rn(inter, den) > IOU_THRESH;
                    }
                    bits = __ballot_sync(0xffffffffu, sup);
                }
                if (lane == 0) s_sup[r * 32 + jb] = bits;
            }
        }
        __syncthreads();
        if (tid < 32) {   // warp 0: serial scan of this chunk
            int done = 0;
            for (int i = c0; i < c1; ++i) {
                unsigned int kw = __shfl_sync(0xffffffffu, keep, i >> 5);
                if ((kw >> (i & 31)) & 1u) {
                    if (tid == 0) s_out[cnt] = i;
                    ++cnt;
                    if (cnt == MAXP) { done = 1; break; }
                    keep &= ~s_sup[i * 32 + tid];
                }
            }
            if (tid == 0) { s_misc[1] = cnt; s_misc[0] = done; }
        }
        __syncthreads();
        if (s_misc[0]) break;
    }

    int outc = s_misc[1];
    for (int e = tid; e < MAXP * 6; e += NT) {
        int p = e / 6, c = e - p * 6;
        float v = 0.0f;
        if (p < outc) {
            int r = s_out[p];
            float4 bx = s_obox[r];
            v = (c == 0) ? bx.x : (c == 1) ? bx.y : (c == 2) ? bx.z :
                (c == 3) ? bx.w : (c == 4) ? s_score[r] : (float)s_cls[r];
        }
        out[b * (MAXP * 6) + e] = v;
    }
}

// ---------------- launch ----------------------------------------------------
extern "C" void kernel_launch(void* const* d_in, const int* in_sizes, int n_in,
                              void* d_out, int out_size) {
    const float* boxes   = (const float*)d_in[0];
    const float* scores  = (const float*)d_in[1];
    const int*   classes = (const int*)d_in[2];
    float* out = (float*)d_out;
    int N = in_sizes[1] / BATCH;

    cudaFuncSetAttribute(k_sortnms,
        cudaFuncAttributeMaxDynamicSharedMemorySize, SMEM_BYTES);

    k_init<<<1, 32>>>();
    dim3 gc(32, BATCH);
    k_collect1<<<gc, 512>>>(scores, N);
    k_check<<<1, 32>>>();
    dim3 gz(8, BATCH);
    k_zeroF<<<gz, 256>>>();
    dim3 gf(32, BATCH);
    k_histF<<<gf, 256>>>(scores, N);
    k_threshF<<<BATCH, 1024>>>();
    k_collect2F<<<gf, 256>>>(scores, N);
    k_sortnms<<<BATCH, NT, SMEM_BYTES>>>(boxes, classes, out, N);
}